// round 15
// baseline (speedup 1.0000x reference)
#include <cuda_runtime.h>
#include <cuda_fp16.h>
#include <math.h>
#include <stdint.h>

// Problem dims (fixed)
#define TOK  8192
#define DIN  1536
#define DH   4096
#define DOUT 2048
#define KCB  8192

// ---------------------------------------------------------------------------
// Scratch (single static device buffer; no cudaMalloc allowed)
// ---------------------------------------------------------------------------
#define OFF_H    ((size_t)0)                         // fp32 H
#define OFF_Z    (OFF_H   + (size_t)TOK*DH*4)        // fp32 Z (post-LN in place)
#define OFF_D    (OFF_Z   + (size_t)TOK*DOUT*4)      // fp16 approx (d - s) [TOK][KCB]
#define OFF_L    (OFF_D   + (size_t)TOK*KCB*2)       // fp16x2 latents
#define OFF_W1   (OFF_L   + (size_t)TOK*DIN*2*2)     // fp16x2 W1
#define OFF_HS   (OFF_W1  + (size_t)DH*DIN*2*2)      // fp16x2 h
#define OFF_W2   (OFF_HS  + (size_t)TOK*DH*2*2)      // fp16x2 W2
#define OFF_Z1   (OFF_W2  + (size_t)DOUT*DH*2*2)     // fp16 z*256
#define OFF_C1   (OFF_Z1  + (size_t)TOK*DOUT*2)      // fp16 cb*8192
#define OFF_S    (OFF_C1  + (size_t)KCB*DOUT*2)
#define OFF_T    (OFF_S   + (size_t)TOK*4)
#define OFF_RMIN (OFF_T   + (size_t)KCB*4)
#define SCRATCH_BYTES (OFF_RMIN + (size_t)TOK*4)

__device__ __align__(1024) unsigned char g_scratch[SCRATCH_BYTES];

__device__ __forceinline__ uint32_t smem_u32(const void* p) {
    uint32_t a;
    asm("{ .reg .u64 t; cvta.to.shared.u64 t, %1; cvt.u32.u64 %0, t; }" : "=r"(a) : "l"(p));
    return a;
}

#define TILE_B   16384                 // 128 rows x 128 bytes

__device__ __forceinline__ void cp16(uint32_t dst, const void* src) {
    asm volatile("cp.async.cg.shared.global [%0], [%1], 16;" :: "r"(dst), "l"(src));
}

// ---------------------------------------------------------------------------
// fp16 2-split GEMM (3 products, error ~2^-26): C = A @ B^T + bias.
// 512 threads (16 warps, 4x4), CTA tile 128x128xK64, warp tile 32x32,
// mma.m16n8k16, 3-stage cp.async. Per-element accumulation order identical
// to the 256-thread version (ks -> sa -> sbp).
// ---------------------------------------------------------------------------
__global__ __launch_bounds__(512)
void gemm_sp2(int N, int K, int nch,
              const __half* __restrict__ A1, const __half* __restrict__ A2,
              const __half* __restrict__ B1, const __half* __restrict__ B2,
              const float* __restrict__ bias, float* __restrict__ C, float ps)
{
    constexpr int NS = 2;
    constexpr int NT = 4;
    constexpr int BUF_B = NT * TILE_B;
    extern __shared__ __align__(1024) unsigned char smem[];
    const uint32_t sb = smem_u32(smem);
    const int tid = threadIdx.x;
    const int lane = tid & 31;
    const int wid = tid >> 5;
    const int warpM = wid >> 2;        // 0..3
    const int warpN = wid & 3;         // 0..3
    const size_t mBase = (size_t)blockIdx.y * 128;
    const size_t nBase = (size_t)blockIdx.x * 128;

    const __half* gsrc[NT] = { A1 + mBase * K, A2 + mBase * K,
                               B1 + nBase * K, B2 + nBase * K };

    auto issue = [&](int t, int b) {
        const uint32_t dbase = sb + b * BUF_B;
        const int kOff = t * 64;
#pragma unroll
        for (int i = 0; i < 8; i++) {
            const int tile = i >> 1;
            const int rv = (i & 1) * 512 + tid;     // 0..1023
            const int r = rv >> 3;
            const int g = rv & 7;
            const uint32_t dst = dbase + tile * TILE_B + r * 128 + ((g ^ (r & 7)) << 4);
            cp16(dst, gsrc[tile] + (size_t)r * K + kOff + g * 8);
        }
        asm volatile("cp.async.commit_group;" ::: "memory");
    };

    float acc[2][4][4];
#pragma unroll
    for (int mi = 0; mi < 2; mi++)
#pragma unroll
        for (int ni = 0; ni < 4; ni++)
#pragma unroll
            for (int r = 0; r < 4; r++) acc[mi][ni][r] = 0.f;

    issue(0, 0);
    if (nch > 1) issue(1, 1);

    for (int t = 0; t < nch; t++) {
        if (t < nch - 1) {
            asm volatile("cp.async.wait_group 1;" ::: "memory");
        } else {
            asm volatile("cp.async.wait_group 0;" ::: "memory");
        }
        __syncthreads();
        if (t + 2 < nch) issue(t + 2, (t + 2) % 3);

        const uint32_t buf = sb + (t % 3) * BUF_B;
#pragma unroll
        for (int ks = 0; ks < 4; ks++) {
            uint32_t bb[NS][4][2];
#pragma unroll
            for (int s = 0; s < NS; s++) {
#pragma unroll
                for (int nh = 0; nh < 2; nh++) {
                    const int nr = warpN * 32 + nh * 16 + (lane >> 4) * 8 + (lane & 7);
                    const int byt = ks * 32 + ((lane >> 3) & 1) * 16;
                    const uint32_t ad = buf + (NS + s) * TILE_B + nr * 128
                                      + (byt ^ ((nr & 7) << 4));
                    uint32_t r0, r1, r2, r3;
                    asm volatile("ldmatrix.sync.aligned.m8n8.x4.shared.b16 "
                                 "{%0,%1,%2,%3}, [%4];"
                                 : "=r"(r0), "=r"(r1), "=r"(r2), "=r"(r3) : "r"(ad));
                    bb[s][nh * 2 + 0][0] = r0; bb[s][nh * 2 + 0][1] = r1;
                    bb[s][nh * 2 + 1][0] = r2; bb[s][nh * 2 + 1][1] = r3;
                }
            }
#pragma unroll
            for (int sa = 0; sa < NS; sa++) {
                uint32_t a[2][4];
                const int row = warpM * 32 + (lane & 15);
                const int byt = ks * 32 + (lane >> 4) * 16;
#pragma unroll
                for (int mi = 0; mi < 2; mi++) {
                    const int rr = row + mi * 16;
                    const uint32_t ad = buf + sa * TILE_B + rr * 128
                                      + (byt ^ ((rr & 7) << 4));
                    asm volatile("ldmatrix.sync.aligned.m8n8.x4.shared.b16 "
                                 "{%0,%1,%2,%3}, [%4];"
                                 : "=r"(a[mi][0]), "=r"(a[mi][1]),
                                   "=r"(a[mi][2]), "=r"(a[mi][3])
                                 : "r"(ad));
                }
                const int nb = NS - sa;
#pragma unroll
                for (int sbp = 0; sbp < NS; sbp++) {
                    if (sbp >= nb) break;
#pragma unroll
                    for (int mi = 0; mi < 2; mi++)
#pragma unroll
                        for (int ni = 0; ni < 4; ni++) {
                            float* c = acc[mi][ni];
                            asm volatile(
                                "mma.sync.aligned.m16n8k16.row.col.f32.f16.f16.f32 "
                                "{%0,%1,%2,%3}, {%4,%5,%6,%7}, {%8,%9}, {%0,%1,%2,%3};"
                                : "+f"(c[0]), "+f"(c[1]), "+f"(c[2]), "+f"(c[3])
                                : "r"(a[mi][0]), "r"(a[mi][1]),
                                  "r"(a[mi][2]), "r"(a[mi][3]),
                                  "r"(bb[sbp][ni][0]), "r"(bb[sbp][ni][1]));
                        }
                }
            }
        }
        __syncthreads();
    }

#pragma unroll
    for (int mi = 0; mi < 2; mi++) {
        const size_t r0 = mBase + warpM * 32 + mi * 16 + (lane >> 2);
        const size_t r1 = r0 + 8;
#pragma unroll
        for (int ni = 0; ni < 4; ni++) {
            const int col = (int)nBase + warpN * 32 + ni * 8 + (lane & 3) * 2;
            float2 v0, v1;
            v0.x = acc[mi][ni][0] * ps + bias[col];
            v0.y = acc[mi][ni][1] * ps + bias[col + 1];
            v1.x = acc[mi][ni][2] * ps + bias[col];
            v1.y = acc[mi][ni][3] * ps + bias[col + 1];
            *(float2*)(C + r0 * N + col) = v0;
            *(float2*)(C + r1 * N + col) = v1;
        }
    }
}

// ---------------------------------------------------------------------------
// GEMM3 (R12 baseline): 1-product fp16 approx, 256 thr, tile 128x128xK64,
// warp tile 64x32, 3-stage cp.async. Epi: Dh = fp16(d - s), per-row min.
// ---------------------------------------------------------------------------
__global__ __launch_bounds__(256)
void gemm3_128(const __half* __restrict__ Z1, const __half* __restrict__ C1,
               const float* __restrict__ S, const float* __restrict__ T,
               __half* __restrict__ Dh, unsigned* __restrict__ rmin)
{
    constexpr int BUF_B = 2 * TILE_B;
    const int K = DOUT;
    const int nch = 32;
    extern __shared__ __align__(1024) unsigned char smem[];
    const uint32_t sb = smem_u32(smem);
    const int tid = threadIdx.x;
    const int lane = tid & 31;
    const int wid = tid >> 5;
    const int warpM = wid >> 2;
    const int warpN = wid & 3;
    const size_t mBase = (size_t)blockIdx.y * 128;
    const size_t nBase = (size_t)blockIdx.x * 128;

    const __half* gsrc[2] = { Z1 + mBase * K, C1 + nBase * K };

    auto issue = [&](int t, int b) {
        const uint32_t dbase = sb + b * BUF_B;
        const int kOff = t * 64;
#pragma unroll
        for (int i = 0; i < 8; i++) {
            const int tile = i >> 2;
            const int r = (i & 3) * 32 + (tid >> 3);
            const int g = tid & 7;
            const uint32_t dst = dbase + tile * TILE_B + r * 128 + ((g ^ (r & 7)) << 4);
            cp16(dst, gsrc[tile] + (size_t)r * K + kOff + g * 8);
        }
        asm volatile("cp.async.commit_group;" ::: "memory");
    };

    float acc[4][4][4];
#pragma unroll
    for (int mi = 0; mi < 4; mi++)
#pragma unroll
        for (int ni = 0; ni < 4; ni++)
#pragma unroll
            for (int r = 0; r < 4; r++) acc[mi][ni][r] = 0.f;

    issue(0, 0);
    issue(1, 1);

    for (int t = 0; t < nch; t++) {
        if (t < nch - 1) {
            asm volatile("cp.async.wait_group 1;" ::: "memory");
        } else {
            asm volatile("cp.async.wait_group 0;" ::: "memory");
        }
        __syncthreads();
        if (t + 2 < nch) issue(t + 2, (t + 2) % 3);

        const uint32_t buf = sb + (t % 3) * BUF_B;
#pragma unroll
        for (int ks = 0; ks < 4; ks++) {
            uint32_t bb[4][2];
#pragma unroll
            for (int nh = 0; nh < 2; nh++) {
                const int nr = warpN * 32 + nh * 16 + (lane >> 4) * 8 + (lane & 7);
                const int byt = ks * 32 + ((lane >> 3) & 1) * 16;
                const uint32_t ad = buf + TILE_B + nr * 128 + (byt ^ ((nr & 7) << 4));
                uint32_t r0, r1, r2, r3;
                asm volatile("ldmatrix.sync.aligned.m8n8.x4.shared.b16 "
                             "{%0,%1,%2,%3}, [%4];"
                             : "=r"(r0), "=r"(r1), "=r"(r2), "=r"(r3) : "r"(ad));
                bb[nh * 2 + 0][0] = r0; bb[nh * 2 + 0][1] = r1;
                bb[nh * 2 + 1][0] = r2; bb[nh * 2 + 1][1] = r3;
            }
            uint32_t a[4][4];
            const int row = warpM * 64 + (lane & 15);
            const int byt = ks * 32 + (lane >> 4) * 16;
#pragma unroll
            for (int mi = 0; mi < 4; mi++) {
                const int rr = row + mi * 16;
                const uint32_t ad = buf + rr * 128 + (byt ^ ((rr & 7) << 4));
                asm volatile("ldmatrix.sync.aligned.m8n8.x4.shared.b16 "
                             "{%0,%1,%2,%3}, [%4];"
                             : "=r"(a[mi][0]), "=r"(a[mi][1]),
                               "=r"(a[mi][2]), "=r"(a[mi][3])
                             : "r"(ad));
            }
#pragma unroll
            for (int mi = 0; mi < 4; mi++)
#pragma unroll
                for (int ni = 0; ni < 4; ni++) {
                    float* c = acc[mi][ni];
                    asm volatile(
                        "mma.sync.aligned.m16n8k16.row.col.f32.f16.f16.f32 "
                        "{%0,%1,%2,%3}, {%4,%5,%6,%7}, {%8,%9}, {%0,%1,%2,%3};"
                        : "+f"(c[0]), "+f"(c[1]), "+f"(c[2]), "+f"(c[3])
                        : "r"(a[mi][0]), "r"(a[mi][1]),
                          "r"(a[mi][2]), "r"(a[mi][3]),
                          "r"(bb[ni][0]), "r"(bb[ni][1]));
                }
        }
        __syncthreads();
    }

    const float ps = 9.5367431640625e-7f;   // 2^-20
    unsigned* red = (unsigned*)smem;
    if (tid < 128) red[tid] = 0xFFFFFFFFu;
    __syncthreads();
#pragma unroll
    for (int mi = 0; mi < 4; mi++) {
        const int rl0 = warpM * 64 + mi * 16 + (lane >> 2);
        const float s0 = S[mBase + rl0];
        const float s1 = S[mBase + rl0 + 8];
        unsigned m0 = 0xFFFFFFFFu, m1 = 0xFFFFFFFFu;
#pragma unroll
        for (int ni = 0; ni < 4; ni++) {
            const int col = (int)nBase + warpN * 32 + ni * 8 + (lane & 3) * 2;
            const float d00 = (s0 + T[col])     - acc[mi][ni][0] * ps;
            const float d01 = (s0 + T[col + 1]) - acc[mi][ni][1] * ps;
            const float d10 = (s1 + T[col])     - acc[mi][ni][2] * ps;
            const float d11 = (s1 + T[col + 1]) - acc[mi][ni][3] * ps;
            const float e00 = d00 - s0, e01 = d01 - s0;
            const float e10 = d10 - s1, e11 = d11 - s1;
            *(__half2*)(Dh + (mBase + rl0) * (size_t)KCB + col) =
                __halves2half2(__float2half_rn(e00), __float2half_rn(e01));
            *(__half2*)(Dh + (mBase + rl0 + 8) * (size_t)KCB + col) =
                __halves2half2(__float2half_rn(e10), __float2half_rn(e11));
#pragma unroll
            for (int jj = 0; jj < 2; jj++) {
                float dv = jj ? e01 : e00;
                unsigned u = __float_as_uint(dv);
                u = (u & 0x80000000u) ? ~u : (u | 0x80000000u);
                m0 = (u < m0) ? u : m0;
                dv = jj ? e11 : e10;
                u = __float_as_uint(dv);
                u = (u & 0x80000000u) ? ~u : (u | 0x80000000u);
                m1 = (u < m1) ? u : m1;
            }
        }
        atomicMin(&red[rl0], m0);
        atomicMin(&red[rl0 + 8], m1);
    }
    __syncthreads();
    if (tid < 128) atomicMin(&rmin[mBase + tid], red[tid]);
}

// ---------------------------------------------------------------------------
// Refine + gather fused: candidate collection, exact double re-rank, output.
// ---------------------------------------------------------------------------
__global__ __launch_bounds__(256)
void refine_gather(const float* __restrict__ Z, const float* __restrict__ CB,
                   const __half* __restrict__ Dh, const unsigned* __restrict__ rmin,
                   const float* __restrict__ S, const float* __restrict__ T,
                   float* __restrict__ out)
{
    __shared__ float zrow[2048];
    __shared__ int cand[128];
    __shared__ int cnt;
    __shared__ unsigned long long bestp;
    const int row = blockIdx.x;
    const int tid = threadIdx.x;
    if (tid == 0) { cnt = 0; bestp = 0xFFFFFFFFFFFFFFFFull; }
    for (int i = tid; i < 2048; i += 256) zrow[i] = Z[(size_t)row * 2048 + i];
    __syncthreads();
    const unsigned mu = rmin[row];
    const float minv = (mu & 0x80000000u) ? __uint_as_float(mu & 0x7FFFFFFFu)
                                          : __uint_as_float(~mu);
    const float thr = minv + 3e-3f;
    const __half* drow = Dh + (size_t)row * KCB;
    for (int j = tid * 8; j < KCB; j += 256 * 8) {
        const uint4 pk = *(const uint4*)(drow + j);
        const unsigned w[4] = {pk.x, pk.y, pk.z, pk.w};
#pragma unroll
        for (int q = 0; q < 4; q++) {
            const __half2 h2 = *(const __half2*)&w[q];
            const float f0 = __low2float(h2);
            const float f1 = __high2float(h2);
            if (f0 <= thr) {
                const int p = atomicAdd(&cnt, 1);
                if (p < 128) cand[p] = j + q * 2;
            }
            if (f1 <= thr) {
                const int p = atomicAdd(&cnt, 1);
                if (p < 128) cand[p] = j + q * 2 + 1;
            }
        }
    }
    __syncthreads();
    const int n = (cnt < 128) ? cnt : 128;
    const float s = S[row];
    for (int t = tid; t < n; t += 256) {
        const int c = cand[t];
        const float* crow = CB + (size_t)c * 2048;
        double m0 = 0, m1 = 0, m2 = 0, m3 = 0;
        for (int i = 0; i < 2048; i += 4) {
            m0 += (double)zrow[i]     * (double)crow[i];
            m1 += (double)zrow[i + 1] * (double)crow[i + 1];
            m2 += (double)zrow[i + 2] * (double)crow[i + 2];
            m3 += (double)zrow[i + 3] * (double)crow[i + 3];
        }
        const float m = (float)((m0 + m1) + (m2 + m3));
        const float d = (s + T[c]) - 2.0f * m;
        unsigned u = __float_as_uint(d);
        u = (u & 0x80000000u) ? ~u : (u | 0x80000000u);
        const unsigned long long p = ((unsigned long long)u << 32) | (unsigned)c;
        atomicMin(&bestp, p);
    }
    __syncthreads();
    // gather: out = z + (cb[best] - z)
    const int best = (int)(bestp & 0xFFFFFFFFull);
    const float* cr = CB + (size_t)best * 2048;
    float* o = out + (size_t)row * 2048;
    for (int i = tid; i < 2048; i += 256) {
        const float zz = zrow[i];
        o[i] = zz + (cr[i] - zz);
    }
}

// ---------------------------------------------------------------------------
// Aux kernels
// ---------------------------------------------------------------------------
__device__ __forceinline__ float block_sum_256(float v) {
    __shared__ float sm[8];
    const int tid = threadIdx.x;
#pragma unroll
    for (int o = 16; o > 0; o >>= 1) v += __shfl_xor_sync(0xFFFFFFFFu, v, o);
    __syncthreads();
    if ((tid & 31) == 0) sm[tid >> 5] = v;
    __syncthreads();
    float r = sm[0];
#pragma unroll
    for (int w = 1; w < 8; w++) r += sm[w];
    return r;
}

__device__ __forceinline__ void split2(float v, __half& h1, __half& h2) {
    h1 = __float2half_rn(v);
    h2 = __float2half_rn(v - __half2float(h1));
}

__device__ __forceinline__ void split2_body(const float* __restrict__ x,
                                            __half* __restrict__ o1,
                                            __half* __restrict__ o2,
                                            int i, float scale)
{
    const float4 v = *(const float4*)(x + (size_t)i * 4);
    __half a[4], b[4];
    split2(v.x * scale, a[0], b[0]);
    split2(v.y * scale, a[1], b[1]);
    split2(v.z * scale, a[2], b[2]);
    split2(v.w * scale, a[3], b[3]);
    *(__half2*)(o1 + (size_t)i * 4)     = __half2{a[0], a[1]};
    *(__half2*)(o1 + (size_t)i * 4 + 2) = __half2{a[2], a[3]};
    *(__half2*)(o2 + (size_t)i * 4)     = __half2{b[0], b[1]};
    *(__half2*)(o2 + (size_t)i * 4 + 2) = __half2{b[2], b[3]};
}

// Fused prep: conversions + rowsq + rmin init (one launch).
#define NBL_L   (TOK * DIN / 4 / 256)
#define NBL_W1  (DH * DIN / 4 / 256)
#define NBL_W2  (DOUT * DH / 4 / 256)
#define NBL_CB  (KCB * DOUT / 4 / 256)
#define NBL_RSQ (KCB)
#define NBL_RM  (TOK / 256)
#define NBL_TOT (NBL_L + NBL_W1 + NBL_W2 + NBL_CB + NBL_RSQ + NBL_RM)

__global__ __launch_bounds__(256)
void prep_kernel(const float* __restrict__ latents, const float* __restrict__ W1,
                 const float* __restrict__ W2, const float* __restrict__ cb,
                 __half* __restrict__ L1, __half* __restrict__ L2,
                 __half* __restrict__ W1a, __half* __restrict__ W1b,
                 __half* __restrict__ W2a, __half* __restrict__ W2b,
                 __half* __restrict__ C1, float* __restrict__ T,
                 unsigned* __restrict__ rmin)
{
    const int b = blockIdx.x;
    const int tid = threadIdx.x;
    if (b < NBL_L) {
        split2_body(latents, L1, L2, b * 256 + tid, 16.0f);
    } else if (b < NBL_L + NBL_W1) {
        split2_body(W1, W1a, W1b, (b - NBL_L) * 256 + tid, 64.0f);
    } else if (b < NBL_L + NBL_W1 + NBL_W2) {
        split2_body(W2, W2a, W2b, (b - NBL_L - NBL_W1) * 256 + tid, 64.0f);
    } else if (b < NBL_L + NBL_W1 + NBL_W2 + NBL_CB) {
        const int i = (b - NBL_L - NBL_W1 - NBL_W2) * 256 + tid;
        const float4 v = *(const float4*)(cb + (size_t)i * 4);
        *(__half2*)(C1 + (size_t)i * 4) =
            __half2{__float2half_rn(v.x * 8192.0f), __float2half_rn(v.y * 8192.0f)};
        *(__half2*)(C1 + (size_t)i * 4 + 2) =
            __half2{__float2half_rn(v.z * 8192.0f), __float2half_rn(v.w * 8192.0f)};
    } else if (b < NBL_L + NBL_W1 + NBL_W2 + NBL_CB + NBL_RSQ) {
        const int r = b - NBL_L - NBL_W1 - NBL_W2 - NBL_CB;
        const float* c = cb + (size_t)r * 2048;
        float q = 0.f;
#pragma unroll
        for (int i = 0; i < 8; i++) { const float cv = c[tid + (i << 8)]; q += cv * cv; }
        const float s = block_sum_256(q);
        if (tid == 0) T[r] = s;
    } else {
        const int i = (b - (NBL_TOT - NBL_RM)) * 256 + tid;
        rmin[i] = 0xFFFFFFFFu;
    }
}

// LayerNorm(4096) + exact-erf GELU -> fp16 split pair (x16)
__global__ void ln_gelu_4096(const float* __restrict__ X,
                             const float* __restrict__ g, const float* __restrict__ b,
                             __half* __restrict__ H1, __half* __restrict__ H2)
{
    const size_t base = (size_t)blockIdx.x * 4096;
    const float* x = X + base;
    const int tid = threadIdx.x;
    float v[16];
    float s = 0.f;
#pragma unroll
    for (int i = 0; i < 16; i++) { v[i] = x[tid + (i << 8)]; s += v[i]; }
    const float mu = block_sum_256(s) * (1.0f / 4096.0f);
    float q = 0.f;
#pragma unroll
    for (int i = 0; i < 16; i++) { const float d = v[i] - mu; q += d * d; }
    const float var = block_sum_256(q) * (1.0f / 4096.0f);
    const float rstd = rsqrtf(var + 1e-5f);
#pragma unroll
    for (int i = 0; i < 16; i++) {
        const int col = tid + (i << 8);
        const float y = (v[i] - mu) * rstd * g[col] + b[col];
        const float act = y * (0.5f * (1.0f + erff(y * 0.70710678118654752440f)));
        __half h1, h2;
        split2(act * 16.0f, h1, h2);
        H1[base + col] = h1; H2[base + col] = h2;
    }
}

// LayerNorm(2048) in place + row sum z^2 + fp16 z*256
__global__ void ln_s_2048(float* __restrict__ X, const float* __restrict__ g,
                          const float* __restrict__ b, float* __restrict__ S,
                          __half* __restrict__ Z1)
{
    const size_t base = (size_t)blockIdx.x * 2048;
    float* x = X + base;
    const int tid = threadIdx.x;
    float v[8];
    float s = 0.f;
#pragma unroll
    for (int i = 0; i < 8; i++) { v[i] = x[tid + (i << 8)]; s += v[i]; }
    const float mu = block_sum_256(s) * (1.0f / 2048.0f);
    float q = 0.f;
#pragma unroll
    for (int i = 0; i < 8; i++) { const float d = v[i] - mu; q += d * d; }
    const float var = block_sum_256(q) * (1.0f / 2048.0f);
    const float rstd = rsqrtf(var + 1e-5f);
    float zs = 0.f;
#pragma unroll
    for (int i = 0; i < 8; i++) {
        const int col = tid + (i << 8);
        const float z = (v[i] - mu) * rstd * g[col] + b[col];
        x[col] = z;
        zs += z * z;
        Z1[base + col] = __float2half_rn(z * 256.0f);
    }
    const float ssum = block_sum_256(zs);
    if (tid == 0) S[blockIdx.x] = ssum;
}

// ---------------------------------------------------------------------------
extern "C" void kernel_launch(void* const* d_in, const int* in_sizes, int n_in,
                              void* d_out, int out_size)
{
    const float* latents = (const float*)d_in[0];
    const float* W1  = (const float*)d_in[1];
    const float* b1  = (const float*)d_in[2];
    const float* g1  = (const float*)d_in[3];
    const float* be1 = (const float*)d_in[4];
    const float* W2  = (const float*)d_in[5];
    const float* b2  = (const float*)d_in[6];
    const float* g2  = (const float*)d_in[7];
    const float* be2 = (const float*)d_in[8];
    const float* cb  = (const float*)d_in[9];
    float* out = (float*)d_out;

    unsigned char* base;
    cudaGetSymbolAddress((void**)&base, g_scratch);
    float* H  = (float*)(base + OFF_H);
    float* Z  = (float*)(base + OFF_Z);
    __half* Dh = (__half*)(base + OFF_D);
    __half* L1 = (__half*)(base + OFF_L);
    __half* L2 = L1 + (size_t)TOK * DIN;
    __half* W1a = (__half*)(base + OFF_W1);
    __half* W1b = W1a + (size_t)DH * DIN;
    __half* Ha = (__half*)(base + OFF_HS);
    __half* Hb = Ha + (size_t)TOK * DH;
    __half* W2a = (__half*)(base + OFF_W2);
    __half* W2b = W2a + (size_t)DOUT * DH;
    __half* Z1 = (__half*)(base + OFF_Z1);
    __half* C1 = (__half*)(base + OFF_C1);
    float* S = (float*)(base + OFF_S);
    float* T = (float*)(base + OFF_T);
    unsigned* rmin = (unsigned*)(base + OFF_RMIN);

    const int SMEM2 = 3 * 4 * TILE_B;   // 196608
    const int SMEM3 = 3 * 2 * TILE_B;   // 98304
    cudaFuncSetAttribute(gemm_sp2, cudaFuncAttributeMaxDynamicSharedMemorySize, SMEM2);
    cudaFuncSetAttribute(gemm3_128, cudaFuncAttributeMaxDynamicSharedMemorySize, SMEM3);

    // #1: fused prep
    prep_kernel<<<NBL_TOT, 256>>>(latents, W1, W2, cb,
                                  L1, L2, W1a, W1b, W2a, W2b, C1, T, rmin);
    // #2: GEMM1: H = (latents @ W1^T) + b1, ps = 2^-10
    gemm_sp2<<<dim3(DH / 128, TOK / 128), 512, SMEM2>>>(
        DH, DIN, DIN / 64, L1, L2, W1a, W1b, b1, H, 0.0009765625f);
    // #3: h = gelu(ln(H)) -> fp16 split pair
    ln_gelu_4096<<<TOK, 256>>>(H, g1, be1, Ha, Hb);
    // #4 (ncu window): GEMM2: Z = (h @ W2^T) + b2
    gemm_sp2<<<dim3(DOUT / 128, TOK / 128), 512, SMEM2>>>(
        DOUT, DH, DH / 64, Ha, Hb, W2a, W2b, b2, Z, 0.0009765625f);
    // #5: z = ln(Z); S = ||z||^2; z -> fp16
    ln_s_2048<<<TOK, 256>>>(Z, g2, be2, S, Z1);
    // #6: GEMM3 (128x128, R12 baseline) -> Dh(d-s, fp16) + per-row min
    gemm3_128<<<dim3(KCB / 128, TOK / 128), 256, SMEM3>>>(Z1, C1, S, T, Dh, rmin);
    // #7: refine + gather fused -> out
    refine_gather<<<TOK, 256>>>(Z, cb, Dh, rmin, S, T, out);
}

// round 16
// speedup vs baseline: 1.0162x; 1.0162x over previous
#include <cuda_runtime.h>
#include <cuda_fp16.h>
#include <math.h>
#include <stdint.h>

// Problem dims (fixed)
#define TOK  8192
#define DIN  1536
#define DH   4096
#define DOUT 2048
#define KCB  8192

// ---------------------------------------------------------------------------
// Scratch (single static device buffer; no cudaMalloc allowed)
// ---------------------------------------------------------------------------
#define OFF_H    ((size_t)0)                         // fp32 H
#define OFF_Z    (OFF_H   + (size_t)TOK*DH*4)        // fp32 Z (post-LN in place)
#define OFF_D    (OFF_Z   + (size_t)TOK*DOUT*4)      // fp16 approx (d - s) [TOK][KCB]
#define OFF_L    (OFF_D   + (size_t)TOK*KCB*2)       // fp16x2 latents
#define OFF_W1   (OFF_L   + (size_t)TOK*DIN*2*2)     // fp16x2 W1
#define OFF_HS   (OFF_W1  + (size_t)DH*DIN*2*2)      // fp16x2 h
#define OFF_W2   (OFF_HS  + (size_t)TOK*DH*2*2)      // fp16x2 W2
#define OFF_Z1   (OFF_W2  + (size_t)DOUT*DH*2*2)     // fp16 z*256
#define OFF_C1   (OFF_Z1  + (size_t)TOK*DOUT*2)      // fp16 cb*8192
#define OFF_S    (OFF_C1  + (size_t)KCB*DOUT*2)
#define OFF_T    (OFF_S   + (size_t)TOK*4)
#define OFF_RMIN (OFF_T   + (size_t)KCB*4)
#define SCRATCH_BYTES (OFF_RMIN + (size_t)TOK*4)

__device__ __align__(1024) unsigned char g_scratch[SCRATCH_BYTES];

__device__ __forceinline__ uint32_t smem_u32(const void* p) {
    uint32_t a;
    asm("{ .reg .u64 t; cvta.to.shared.u64 t, %1; cvt.u32.u64 %0, t; }" : "=r"(a) : "l"(p));
    return a;
}

#define TILE_B   16384                 // 128 rows x 128 bytes

__device__ __forceinline__ void cp16(uint32_t dst, const void* src) {
    asm volatile("cp.async.cg.shared.global [%0], [%1], 16;" :: "r"(dst), "l"(src));
}

// ---------------------------------------------------------------------------
// fp16 2-split GEMM (3 products, error ~2^-26): C = A @ B^T + bias.
// 256 thr (8 warps 2x4), CTA tile 128x128xK64, warp tile 64x32,
// mma.m16n8k16, 3-stage cp.async.  (Proven optimum: tensor 76%, 894us ncu.)
// ---------------------------------------------------------------------------
__global__ __launch_bounds__(256)
void gemm_sp2(int N, int K, int nch,
              const __half* __restrict__ A1, const __half* __restrict__ A2,
              const __half* __restrict__ B1, const __half* __restrict__ B2,
              const float* __restrict__ bias, float* __restrict__ C, float ps)
{
    constexpr int NS = 2;
    constexpr int NT = 4;
    constexpr int BUF_B = NT * TILE_B;
    extern __shared__ __align__(1024) unsigned char smem[];
    const uint32_t sb = smem_u32(smem);
    const int tid = threadIdx.x;
    const int lane = tid & 31;
    const int wid = tid >> 5;
    const int warpM = wid >> 2;
    const int warpN = wid & 3;
    const size_t mBase = (size_t)blockIdx.y * 128;
    const size_t nBase = (size_t)blockIdx.x * 128;

    const __half* gsrc[NT] = { A1 + mBase * K, A2 + mBase * K,
                               B1 + nBase * K, B2 + nBase * K };

    auto issue = [&](int t, int b) {
        const uint32_t dbase = sb + b * BUF_B;
        const int kOff = t * 64;
#pragma unroll
        for (int i = 0; i < 4 * NT; i++) {
            const int tile = i >> 2;
            const int r = (i & 3) * 32 + (tid >> 3);
            const int g = tid & 7;
            const uint32_t dst = dbase + tile * TILE_B + r * 128 + ((g ^ (r & 7)) << 4);
            cp16(dst, gsrc[tile] + (size_t)r * K + kOff + g * 8);
        }
        asm volatile("cp.async.commit_group;" ::: "memory");
    };

    float acc[4][4][4];
#pragma unroll
    for (int mi = 0; mi < 4; mi++)
#pragma unroll
        for (int ni = 0; ni < 4; ni++)
#pragma unroll
            for (int r = 0; r < 4; r++) acc[mi][ni][r] = 0.f;

    issue(0, 0);
    if (nch > 1) issue(1, 1);

    for (int t = 0; t < nch; t++) {
        if (t < nch - 1) {
            asm volatile("cp.async.wait_group 1;" ::: "memory");
        } else {
            asm volatile("cp.async.wait_group 0;" ::: "memory");
        }
        __syncthreads();
        if (t + 2 < nch) issue(t + 2, (t + 2) % 3);

        const uint32_t buf = sb + (t % 3) * BUF_B;
#pragma unroll
        for (int ks = 0; ks < 4; ks++) {
            uint32_t bb[NS][4][2];
#pragma unroll
            for (int s = 0; s < NS; s++) {
#pragma unroll
                for (int nh = 0; nh < 2; nh++) {
                    const int nr = warpN * 32 + nh * 16 + (lane >> 4) * 8 + (lane & 7);
                    const int byt = ks * 32 + ((lane >> 3) & 1) * 16;
                    const uint32_t ad = buf + (NS + s) * TILE_B + nr * 128
                                      + (byt ^ ((nr & 7) << 4));
                    uint32_t r0, r1, r2, r3;
                    asm volatile("ldmatrix.sync.aligned.m8n8.x4.shared.b16 "
                                 "{%0,%1,%2,%3}, [%4];"
                                 : "=r"(r0), "=r"(r1), "=r"(r2), "=r"(r3) : "r"(ad));
                    bb[s][nh * 2 + 0][0] = r0; bb[s][nh * 2 + 0][1] = r1;
                    bb[s][nh * 2 + 1][0] = r2; bb[s][nh * 2 + 1][1] = r3;
                }
            }
#pragma unroll
            for (int sa = 0; sa < NS; sa++) {
                uint32_t a[4][4];
                const int row = warpM * 64 + (lane & 15);
                const int byt = ks * 32 + (lane >> 4) * 16;
#pragma unroll
                for (int mi = 0; mi < 4; mi++) {
                    const int rr = row + mi * 16;
                    const uint32_t ad = buf + sa * TILE_B + rr * 128
                                      + (byt ^ ((rr & 7) << 4));
                    asm volatile("ldmatrix.sync.aligned.m8n8.x4.shared.b16 "
                                 "{%0,%1,%2,%3}, [%4];"
                                 : "=r"(a[mi][0]), "=r"(a[mi][1]),
                                   "=r"(a[mi][2]), "=r"(a[mi][3])
                                 : "r"(ad));
                }
                const int nb = NS - sa;
#pragma unroll
                for (int sbp = 0; sbp < NS; sbp++) {
                    if (sbp >= nb) break;
#pragma unroll
                    for (int mi = 0; mi < 4; mi++)
#pragma unroll
                        for (int ni = 0; ni < 4; ni++) {
                            float* c = acc[mi][ni];
                            asm volatile(
                                "mma.sync.aligned.m16n8k16.row.col.f32.f16.f16.f32 "
                                "{%0,%1,%2,%3}, {%4,%5,%6,%7}, {%8,%9}, {%0,%1,%2,%3};"
                                : "+f"(c[0]), "+f"(c[1]), "+f"(c[2]), "+f"(c[3])
                                : "r"(a[mi][0]), "r"(a[mi][1]),
                                  "r"(a[mi][2]), "r"(a[mi][3]),
                                  "r"(bb[sbp][ni][0]), "r"(bb[sbp][ni][1]));
                        }
                }
            }
        }
        __syncthreads();
    }

#pragma unroll
    for (int mi = 0; mi < 4; mi++) {
        const size_t r0 = mBase + warpM * 64 + mi * 16 + (lane >> 2);
        const size_t r1 = r0 + 8;
#pragma unroll
        for (int ni = 0; ni < 4; ni++) {
            const int col = (int)nBase + warpN * 32 + ni * 8 + (lane & 3) * 2;
            float2 v0, v1;
            v0.x = acc[mi][ni][0] * ps + bias[col];
            v0.y = acc[mi][ni][1] * ps + bias[col + 1];
            v1.x = acc[mi][ni][2] * ps + bias[col];
            v1.y = acc[mi][ni][3] * ps + bias[col + 1];
            *(float2*)(C + r0 * N + col) = v0;
            *(float2*)(C + r1 * N + col) = v1;
        }
    }
}

// ---------------------------------------------------------------------------
// GEMM3 (R12 baseline): 1-product fp16 approx, 256 thr, tile 128x128xK64,
// warp tile 64x32, 3-stage cp.async. Epi: Dh = fp16(d - s), per-row min.
// ---------------------------------------------------------------------------
__global__ __launch_bounds__(256)
void gemm3_128(const __half* __restrict__ Z1, const __half* __restrict__ C1,
               const float* __restrict__ S, const float* __restrict__ T,
               __half* __restrict__ Dh, unsigned* __restrict__ rmin)
{
    constexpr int BUF_B = 2 * TILE_B;
    const int K = DOUT;
    const int nch = 32;
    extern __shared__ __align__(1024) unsigned char smem[];
    const uint32_t sb = smem_u32(smem);
    const int tid = threadIdx.x;
    const int lane = tid & 31;
    const int wid = tid >> 5;
    const int warpM = wid >> 2;
    const int warpN = wid & 3;
    const size_t mBase = (size_t)blockIdx.y * 128;
    const size_t nBase = (size_t)blockIdx.x * 128;

    const __half* gsrc[2] = { Z1 + mBase * K, C1 + nBase * K };

    auto issue = [&](int t, int b) {
        const uint32_t dbase = sb + b * BUF_B;
        const int kOff = t * 64;
#pragma unroll
        for (int i = 0; i < 8; i++) {
            const int tile = i >> 2;
            const int r = (i & 3) * 32 + (tid >> 3);
            const int g = tid & 7;
            const uint32_t dst = dbase + tile * TILE_B + r * 128 + ((g ^ (r & 7)) << 4);
            cp16(dst, gsrc[tile] + (size_t)r * K + kOff + g * 8);
        }
        asm volatile("cp.async.commit_group;" ::: "memory");
    };

    float acc[4][4][4];
#pragma unroll
    for (int mi = 0; mi < 4; mi++)
#pragma unroll
        for (int ni = 0; ni < 4; ni++)
#pragma unroll
            for (int r = 0; r < 4; r++) acc[mi][ni][r] = 0.f;

    issue(0, 0);
    issue(1, 1);

    for (int t = 0; t < nch; t++) {
        if (t < nch - 1) {
            asm volatile("cp.async.wait_group 1;" ::: "memory");
        } else {
            asm volatile("cp.async.wait_group 0;" ::: "memory");
        }
        __syncthreads();
        if (t + 2 < nch) issue(t + 2, (t + 2) % 3);

        const uint32_t buf = sb + (t % 3) * BUF_B;
#pragma unroll
        for (int ks = 0; ks < 4; ks++) {
            uint32_t bb[4][2];
#pragma unroll
            for (int nh = 0; nh < 2; nh++) {
                const int nr = warpN * 32 + nh * 16 + (lane >> 4) * 8 + (lane & 7);
                const int byt = ks * 32 + ((lane >> 3) & 1) * 16;
                const uint32_t ad = buf + TILE_B + nr * 128 + (byt ^ ((nr & 7) << 4));
                uint32_t r0, r1, r2, r3;
                asm volatile("ldmatrix.sync.aligned.m8n8.x4.shared.b16 "
                             "{%0,%1,%2,%3}, [%4];"
                             : "=r"(r0), "=r"(r1), "=r"(r2), "=r"(r3) : "r"(ad));
                bb[nh * 2 + 0][0] = r0; bb[nh * 2 + 0][1] = r1;
                bb[nh * 2 + 1][0] = r2; bb[nh * 2 + 1][1] = r3;
            }
            uint32_t a[4][4];
            const int row = warpM * 64 + (lane & 15);
            const int byt = ks * 32 + (lane >> 4) * 16;
#pragma unroll
            for (int mi = 0; mi < 4; mi++) {
                const int rr = row + mi * 16;
                const uint32_t ad = buf + rr * 128 + (byt ^ ((rr & 7) << 4));
                asm volatile("ldmatrix.sync.aligned.m8n8.x4.shared.b16 "
                             "{%0,%1,%2,%3}, [%4];"
                             : "=r"(a[mi][0]), "=r"(a[mi][1]),
                               "=r"(a[mi][2]), "=r"(a[mi][3])
                             : "r"(ad));
            }
#pragma unroll
            for (int mi = 0; mi < 4; mi++)
#pragma unroll
                for (int ni = 0; ni < 4; ni++) {
                    float* c = acc[mi][ni];
                    asm volatile(
                        "mma.sync.aligned.m16n8k16.row.col.f32.f16.f16.f32 "
                        "{%0,%1,%2,%3}, {%4,%5,%6,%7}, {%8,%9}, {%0,%1,%2,%3};"
                        : "+f"(c[0]), "+f"(c[1]), "+f"(c[2]), "+f"(c[3])
                        : "r"(a[mi][0]), "r"(a[mi][1]),
                          "r"(a[mi][2]), "r"(a[mi][3]),
                          "r"(bb[ni][0]), "r"(bb[ni][1]));
                }
        }
        __syncthreads();
    }

    const float ps = 9.5367431640625e-7f;   // 2^-20
    unsigned* red = (unsigned*)smem;
    if (tid < 128) red[tid] = 0xFFFFFFFFu;
    __syncthreads();
#pragma unroll
    for (int mi = 0; mi < 4; mi++) {
        const int rl0 = warpM * 64 + mi * 16 + (lane >> 2);
        const float s0 = S[mBase + rl0];
        const float s1 = S[mBase + rl0 + 8];
        unsigned m0 = 0xFFFFFFFFu, m1 = 0xFFFFFFFFu;
#pragma unroll
        for (int ni = 0; ni < 4; ni++) {
            const int col = (int)nBase + warpN * 32 + ni * 8 + (lane & 3) * 2;
            const float d00 = (s0 + T[col])     - acc[mi][ni][0] * ps;
            const float d01 = (s0 + T[col + 1]) - acc[mi][ni][1] * ps;
            const float d10 = (s1 + T[col])     - acc[mi][ni][2] * ps;
            const float d11 = (s1 + T[col + 1]) - acc[mi][ni][3] * ps;
            const float e00 = d00 - s0, e01 = d01 - s0;
            const float e10 = d10 - s1, e11 = d11 - s1;
            *(__half2*)(Dh + (mBase + rl0) * (size_t)KCB + col) =
                __halves2half2(__float2half_rn(e00), __float2half_rn(e01));
            *(__half2*)(Dh + (mBase + rl0 + 8) * (size_t)KCB + col) =
                __halves2half2(__float2half_rn(e10), __float2half_rn(e11));
#pragma unroll
            for (int jj = 0; jj < 2; jj++) {
                float dv = jj ? e01 : e00;
                unsigned u = __float_as_uint(dv);
                u = (u & 0x80000000u) ? ~u : (u | 0x80000000u);
                m0 = (u < m0) ? u : m0;
                dv = jj ? e11 : e10;
                u = __float_as_uint(dv);
                u = (u & 0x80000000u) ? ~u : (u | 0x80000000u);
                m1 = (u < m1) ? u : m1;
            }
        }
        atomicMin(&red[rl0], m0);
        atomicMin(&red[rl0 + 8], m1);
    }
    __syncthreads();
    if (tid < 128) atomicMin(&rmin[mBase + tid], red[tid]);
}

// ---------------------------------------------------------------------------
// Refine + gather fused: candidate collection, exact double re-rank, output.
// ---------------------------------------------------------------------------
__global__ __launch_bounds__(256)
void refine_gather(const float* __restrict__ Z, const float* __restrict__ CB,
                   const __half* __restrict__ Dh, const unsigned* __restrict__ rmin,
                   const float* __restrict__ S, const float* __restrict__ T,
                   float* __restrict__ out)
{
    __shared__ float zrow[2048];
    __shared__ int cand[128];
    __shared__ int cnt;
    __shared__ unsigned long long bestp;
    const int row = blockIdx.x;
    const int tid = threadIdx.x;
    if (tid == 0) { cnt = 0; bestp = 0xFFFFFFFFFFFFFFFFull; }
    for (int i = tid; i < 2048; i += 256) zrow[i] = Z[(size_t)row * 2048 + i];
    __syncthreads();
    const unsigned mu = rmin[row];
    const float minv = (mu & 0x80000000u) ? __uint_as_float(mu & 0x7FFFFFFFu)
                                          : __uint_as_float(~mu);
    const float thr = minv + 3e-3f;
    const __half* drow = Dh + (size_t)row * KCB;
    for (int j = tid * 8; j < KCB; j += 256 * 8) {
        const uint4 pk = *(const uint4*)(drow + j);
        const unsigned w[4] = {pk.x, pk.y, pk.z, pk.w};
#pragma unroll
        for (int q = 0; q < 4; q++) {
            const __half2 h2 = *(const __half2*)&w[q];
            const float f0 = __low2float(h2);
            const float f1 = __high2float(h2);
            if (f0 <= thr) {
                const int p = atomicAdd(&cnt, 1);
                if (p < 128) cand[p] = j + q * 2;
            }
            if (f1 <= thr) {
                const int p = atomicAdd(&cnt, 1);
                if (p < 128) cand[p] = j + q * 2 + 1;
            }
        }
    }
    __syncthreads();
    const int n = (cnt < 128) ? cnt : 128;
    const float s = S[row];
    for (int t = tid; t < n; t += 256) {
        const int c = cand[t];
        const float* crow = CB + (size_t)c * 2048;
        double m0 = 0, m1 = 0, m2 = 0, m3 = 0;
        for (int i = 0; i < 2048; i += 4) {
            m0 += (double)zrow[i]     * (double)crow[i];
            m1 += (double)zrow[i + 1] * (double)crow[i + 1];
            m2 += (double)zrow[i + 2] * (double)crow[i + 2];
            m3 += (double)zrow[i + 3] * (double)crow[i + 3];
        }
        const float m = (float)((m0 + m1) + (m2 + m3));
        const float d = (s + T[c]) - 2.0f * m;
        unsigned u = __float_as_uint(d);
        u = (u & 0x80000000u) ? ~u : (u | 0x80000000u);
        const unsigned long long p = ((unsigned long long)u << 32) | (unsigned)c;
        atomicMin(&bestp, p);
    }
    __syncthreads();
    // gather: out = z + (cb[best] - z)
    const int best = (int)(bestp & 0xFFFFFFFFull);
    const float* cr = CB + (size_t)best * 2048;
    float* o = out + (size_t)row * 2048;
    for (int i = tid; i < 2048; i += 256) {
        const float zz = zrow[i];
        o[i] = zz + (cr[i] - zz);
    }
}

// ---------------------------------------------------------------------------
// Aux kernels
// ---------------------------------------------------------------------------
__device__ __forceinline__ float block_sum_256(float v) {
    __shared__ float sm[8];
    const int tid = threadIdx.x;
#pragma unroll
    for (int o = 16; o > 0; o >>= 1) v += __shfl_xor_sync(0xFFFFFFFFu, v, o);
    __syncthreads();
    if ((tid & 31) == 0) sm[tid >> 5] = v;
    __syncthreads();
    float r = sm[0];
#pragma unroll
    for (int w = 1; w < 8; w++) r += sm[w];
    return r;
}

__device__ __forceinline__ void split2(float v, __half& h1, __half& h2) {
    h1 = __float2half_rn(v);
    h2 = __float2half_rn(v - __half2float(h1));
}

__device__ __forceinline__ void split2_body(const float* __restrict__ x,
                                            __half* __restrict__ o1,
                                            __half* __restrict__ o2,
                                            int i, float scale)
{
    const float4 v = *(const float4*)(x + (size_t)i * 4);
    __half a[4], b[4];
    split2(v.x * scale, a[0], b[0]);
    split2(v.y * scale, a[1], b[1]);
    split2(v.z * scale, a[2], b[2]);
    split2(v.w * scale, a[3], b[3]);
    *(__half2*)(o1 + (size_t)i * 4)     = __half2{a[0], a[1]};
    *(__half2*)(o1 + (size_t)i * 4 + 2) = __half2{a[2], a[3]};
    *(__half2*)(o2 + (size_t)i * 4)     = __half2{b[0], b[1]};
    *(__half2*)(o2 + (size_t)i * 4 + 2) = __half2{b[2], b[3]};
}

// Fused prep: conversions + rowsq + rmin init (one launch).
#define NBL_L   (TOK * DIN / 4 / 256)
#define NBL_W1  (DH * DIN / 4 / 256)
#define NBL_W2  (DOUT * DH / 4 / 256)
#define NBL_CB  (KCB * DOUT / 4 / 256)
#define NBL_RSQ (KCB)
#define NBL_RM  (TOK / 256)
#define NBL_TOT (NBL_L + NBL_W1 + NBL_W2 + NBL_CB + NBL_RSQ + NBL_RM)

__global__ __launch_bounds__(256)
void prep_kernel(const float* __restrict__ latents, const float* __restrict__ W1,
                 const float* __restrict__ W2, const float* __restrict__ cb,
                 __half* __restrict__ L1, __half* __restrict__ L2,
                 __half* __restrict__ W1a, __half* __restrict__ W1b,
                 __half* __restrict__ W2a, __half* __restrict__ W2b,
                 __half* __restrict__ C1, float* __restrict__ T,
                 unsigned* __restrict__ rmin)
{
    const int b = blockIdx.x;
    const int tid = threadIdx.x;
    if (b < NBL_L) {
        split2_body(latents, L1, L2, b * 256 + tid, 16.0f);
    } else if (b < NBL_L + NBL_W1) {
        split2_body(W1, W1a, W1b, (b - NBL_L) * 256 + tid, 64.0f);
    } else if (b < NBL_L + NBL_W1 + NBL_W2) {
        split2_body(W2, W2a, W2b, (b - NBL_L - NBL_W1) * 256 + tid, 64.0f);
    } else if (b < NBL_L + NBL_W1 + NBL_W2 + NBL_CB) {
        const int i = (b - NBL_L - NBL_W1 - NBL_W2) * 256 + tid;
        const float4 v = *(const float4*)(cb + (size_t)i * 4);
        *(__half2*)(C1 + (size_t)i * 4) =
            __half2{__float2half_rn(v.x * 8192.0f), __float2half_rn(v.y * 8192.0f)};
        *(__half2*)(C1 + (size_t)i * 4 + 2) =
            __half2{__float2half_rn(v.z * 8192.0f), __float2half_rn(v.w * 8192.0f)};
    } else if (b < NBL_L + NBL_W1 + NBL_W2 + NBL_CB + NBL_RSQ) {
        const int r = b - NBL_L - NBL_W1 - NBL_W2 - NBL_CB;
        const float* c = cb + (size_t)r * 2048;
        float q = 0.f;
#pragma unroll
        for (int i = 0; i < 8; i++) { const float cv = c[tid + (i << 8)]; q += cv * cv; }
        const float s = block_sum_256(q);
        if (tid == 0) T[r] = s;
    } else {
        const int i = (b - (NBL_TOT - NBL_RM)) * 256 + tid;
        rmin[i] = 0xFFFFFFFFu;
    }
}

// LayerNorm(4096) + exact-erf GELU -> fp16 split pair (x16)
__global__ void ln_gelu_4096(const float* __restrict__ X,
                             const float* __restrict__ g, const float* __restrict__ b,
                             __half* __restrict__ H1, __half* __restrict__ H2)
{
    const size_t base = (size_t)blockIdx.x * 4096;
    const float* x = X + base;
    const int tid = threadIdx.x;
    float v[16];
    float s = 0.f;
#pragma unroll
    for (int i = 0; i < 16; i++) { v[i] = x[tid + (i << 8)]; s += v[i]; }
    const float mu = block_sum_256(s) * (1.0f / 4096.0f);
    float q = 0.f;
#pragma unroll
    for (int i = 0; i < 16; i++) { const float d = v[i] - mu; q += d * d; }
    const float var = block_sum_256(q) * (1.0f / 4096.0f);
    const float rstd = rsqrtf(var + 1e-5f);
#pragma unroll
    for (int i = 0; i < 16; i++) {
        const int col = tid + (i << 8);
        const float y = (v[i] - mu) * rstd * g[col] + b[col];
        const float act = y * (0.5f * (1.0f + erff(y * 0.70710678118654752440f)));
        __half h1, h2;
        split2(act * 16.0f, h1, h2);
        H1[base + col] = h1; H2[base + col] = h2;
    }
}

// LayerNorm(2048) in place + row sum z^2 + fp16 z*256
__global__ void ln_s_2048(float* __restrict__ X, const float* __restrict__ g,
                          const float* __restrict__ b, float* __restrict__ S,
                          __half* __restrict__ Z1)
{
    const size_t base = (size_t)blockIdx.x * 2048;
    float* x = X + base;
    const int tid = threadIdx.x;
    float v[8];
    float s = 0.f;
#pragma unroll
    for (int i = 0; i < 8; i++) { v[i] = x[tid + (i << 8)]; s += v[i]; }
    const float mu = block_sum_256(s) * (1.0f / 2048.0f);
    float q = 0.f;
#pragma unroll
    for (int i = 0; i < 8; i++) { const float d = v[i] - mu; q += d * d; }
    const float var = block_sum_256(q) * (1.0f / 2048.0f);
    const float rstd = rsqrtf(var + 1e-5f);
    float zs = 0.f;
#pragma unroll
    for (int i = 0; i < 8; i++) {
        const int col = tid + (i << 8);
        const float z = (v[i] - mu) * rstd * g[col] + b[col];
        x[col] = z;
        zs += z * z;
        Z1[base + col] = __float2half_rn(z * 256.0f);
    }
    const float ssum = block_sum_256(zs);
    if (tid == 0) S[blockIdx.x] = ssum;
}

// ---------------------------------------------------------------------------
extern "C" void kernel_launch(void* const* d_in, const int* in_sizes, int n_in,
                              void* d_out, int out_size)
{
    const float* latents = (const float*)d_in[0];
    const float* W1  = (const float*)d_in[1];
    const float* b1  = (const float*)d_in[2];
    const float* g1  = (const float*)d_in[3];
    const float* be1 = (const float*)d_in[4];
    const float* W2  = (const float*)d_in[5];
    const float* b2  = (const float*)d_in[6];
    const float* g2  = (const float*)d_in[7];
    const float* be2 = (const float*)d_in[8];
    const float* cb  = (const float*)d_in[9];
    float* out = (float*)d_out;

    unsigned char* base;
    cudaGetSymbolAddress((void**)&base, g_scratch);
    float* H  = (float*)(base + OFF_H);
    float* Z  = (float*)(base + OFF_Z);
    __half* Dh = (__half*)(base + OFF_D);
    __half* L1 = (__half*)(base + OFF_L);
    __half* L2 = L1 + (size_t)TOK * DIN;
    __half* W1a = (__half*)(base + OFF_W1);
    __half* W1b = W1a + (size_t)DH * DIN;
    __half* Ha = (__half*)(base + OFF_HS);
    __half* Hb = Ha + (size_t)TOK * DH;
    __half* W2a = (__half*)(base + OFF_W2);
    __half* W2b = W2a + (size_t)DOUT * DH;
    __half* Z1 = (__half*)(base + OFF_Z1);
    __half* C1 = (__half*)(base + OFF_C1);
    float* S = (float*)(base + OFF_S);
    float* T = (float*)(base + OFF_T);
    unsigned* rmin = (unsigned*)(base + OFF_RMIN);

    const int SMEM2 = 3 * 4 * TILE_B;   // 196608
    const int SMEM3 = 3 * 2 * TILE_B;   // 98304
    cudaFuncSetAttribute(gemm_sp2, cudaFuncAttributeMaxDynamicSharedMemorySize, SMEM2);
    cudaFuncSetAttribute(gemm3_128, cudaFuncAttributeMaxDynamicSharedMemorySize, SMEM3);

    // #1: fused prep
    prep_kernel<<<NBL_TOT, 256>>>(latents, W1, W2, cb,
                                  L1, L2, W1a, W1b, W2a, W2b, C1, T, rmin);
    // #2: GEMM1: H = (latents @ W1^T) + b1, ps = 2^-10
    gemm_sp2<<<dim3(DH / 128, TOK / 128), 256, SMEM2>>>(
        DH, DIN, DIN / 64, L1, L2, W1a, W1b, b1, H, 0.0009765625f);
    // #3: h = gelu(ln(H)) -> fp16 split pair
    ln_gelu_4096<<<TOK, 256>>>(H, g1, be1, Ha, Hb);
    // #4: GEMM2: Z = (h @ W2^T) + b2
    gemm_sp2<<<dim3(DOUT / 128, TOK / 128), 256, SMEM2>>>(
        DOUT, DH, DH / 64, Ha, Hb, W2a, W2b, b2, Z, 0.0009765625f);
    // #5: z = ln(Z); S = ||z||^2; z -> fp16
    ln_s_2048<<<TOK, 256>>>(Z, g2, be2, S, Z1);
    // #6: GEMM3 (128x128) -> Dh(d-s, fp16) + per-row min
    gemm3_128<<<dim3(KCB / 128, TOK / 128), 256, SMEM3>>>(Z1, C1, S, T, Dh, rmin);
    // #7: refine + gather fused -> out
    refine_gather<<<TOK, 256>>>(Z, cb, Dh, rmin, S, T, out);
}